// round 6
// baseline (speedup 1.0000x reference)
#include <cuda_runtime.h>
#include <math.h>

// ---------------- problem constants ----------------
#define NN 131072
#define EE 2097152
#define BB 128
#define NPG 1024
#define HH 128
#define TT 8

// ---------------- device scratch ----------------
__device__ float g_x[NN * HH];
__device__ float g_x2[NN * HH];
__device__ float g_k[NN * HH];
__device__ float g_v[NN * HH];
__device__ float g_q[TT * HH];
__device__ float g_o[BB * TT * HH];
__device__ float g_tok[BB * TT * HH];
__device__ float g_gf[BB * HH];
__device__ float g_gs[BB * HH];

__device__ int g_deg[NN];
__device__ int g_start[NN];
__device__ int g_cursor[NN];
__device__ int g_eid[EE];
__device__ int g_bsum[NN / 1024];
__device__ int g_bbase[NN / 1024];

// ---------------- CSR build ----------------
__global__ void k_degree(const int* __restrict__ ei) {
    int e = blockIdx.x * 256 + threadIdx.x;
    if (e < EE) atomicAdd(&g_deg[ei[EE + e]], 1);
}

__global__ void k_scan1() {
    __shared__ int wsum[32];
    int i = blockIdx.x * 1024 + threadIdx.x;
    int lane = threadIdx.x & 31, wid = threadIdx.x >> 5;
    int s = g_deg[i];
    #pragma unroll
    for (int d = 1; d < 32; d <<= 1) {
        int t = __shfl_up_sync(0xffffffffu, s, d);
        if (lane >= d) s += t;
    }
    if (lane == 31) wsum[wid] = s;
    __syncthreads();
    if (wid == 0) {
        int ws = wsum[lane];
        #pragma unroll
        for (int d = 1; d < 32; d <<= 1) {
            int t = __shfl_up_sync(0xffffffffu, ws, d);
            if (lane >= d) ws += t;
        }
        wsum[lane] = ws;
    }
    __syncthreads();
    int incl = s + (wid > 0 ? wsum[wid - 1] : 0);
    g_start[i] = incl;
    if (threadIdx.x == 1023) g_bsum[blockIdx.x] = incl;
}

// warp-parallel scan of the 128 block sums
__global__ void k_scan2() {
    int lane = threadIdx.x;  // 32 threads
    int base = lane * 4;
    int s0 = g_bsum[base], s1 = g_bsum[base + 1], s2 = g_bsum[base + 2], s3 = g_bsum[base + 3];
    int tot = s0 + s1 + s2 + s3;
    int pre = tot;
    #pragma unroll
    for (int d = 1; d < 32; d <<= 1) {
        int t = __shfl_up_sync(0xffffffffu, pre, d);
        if (lane >= d) pre += t;
    }
    pre -= tot;  // exclusive
    g_bbase[base] = pre;
    g_bbase[base + 1] = pre + s0;
    g_bbase[base + 2] = pre + s0 + s1;
    g_bbase[base + 3] = pre + s0 + s1 + s2;
}

__global__ void k_scan3() {
    int i = blockIdx.x * 256 + threadIdx.x;
    if (i < NN) g_start[i] = g_start[i] - g_deg[i] + g_bbase[i >> 10];
}

__global__ void k_scatter(const int* __restrict__ ei) {
    int e = blockIdx.x * 256 + threadIdx.x;
    if (e < EE) {
        int d = ei[EE + e];
        int p = atomicAdd(&g_cursor[d], 1);
        g_eid[g_start[d] + p] = ei[e];
    }
}

// ============================================================================
// Fused GIN layer: out = (gather(X) if gather else X) @ W + bias (+ addv[graph])
// 128x128 block tile, 256 threads, A fully resident in smem (row-major,
// stride 132), B streamed in 8-k chunks, double-buffered.
// ============================================================================
#define SMEM_GIN ((128 * 132 + 2 * 8 * 128) * 4)

__device__ __forceinline__ void gemm_panel(
    const float* __restrict__ sA, float* __restrict__ sB,
    const float* __restrict__ W, int w_ld,
    const float* __restrict__ bias, const float* __restrict__ addv,
    float* __restrict__ out, size_t row0, int tid)
{
    int lb_k = tid >> 5, lb_j = (tid & 31) * 4;
    const float* Wp = W + (size_t)lb_k * w_ld + lb_j;
    float4 rb = __ldg((const float4*)Wp);
    *(float4*)&sB[lb_k * 128 + lb_j] = rb;
    __syncthreads();

    int ty = tid >> 4, tx = tid & 15;
    int r4 = ty * 4, c4 = tx * 4;
    float acc[8][8] = {};

    #pragma unroll 1
    for (int ch = 0; ch < 16; ch++) {
        int buf = ch & 1;
        if (ch < 15) rb = __ldg((const float4*)(Wp + (size_t)(ch + 1) * 8 * w_ld));
        #pragma unroll
        for (int k = 0; k < 8; k++) {
            int kk = ch * 8 + k;
            float av[8], bv[8];
            #pragma unroll
            for (int m = 0; m < 4; m++) {
                av[m]     = sA[(r4 + m) * 132 + kk];
                av[4 + m] = sA[(64 + r4 + m) * 132 + kk];
            }
            float4 b0 = *(const float4*)&sB[buf * 1024 + k * 128 + c4];
            float4 b1 = *(const float4*)&sB[buf * 1024 + k * 128 + 64 + c4];
            bv[0] = b0.x; bv[1] = b0.y; bv[2] = b0.z; bv[3] = b0.w;
            bv[4] = b1.x; bv[5] = b1.y; bv[6] = b1.z; bv[7] = b1.w;
            #pragma unroll
            for (int i = 0; i < 8; i++)
                #pragma unroll
                for (int j = 0; j < 8; j++)
                    acc[i][j] += av[i] * bv[j];
        }
        if (ch < 15) {
            *(float4*)&sB[(buf ^ 1) * 1024 + lb_k * 128 + lb_j] = rb;
            __syncthreads();
        }
    }

    float4 bv0 = *(const float4*)&bias[c4];
    float4 bv1 = *(const float4*)&bias[64 + c4];
    float bb[8] = {bv0.x, bv0.y, bv0.z, bv0.w, bv1.x, bv1.y, bv1.z, bv1.w};
    if (addv) {
        const float* av = addv + (row0 >> 10) * 128;
        float4 g0 = __ldg((const float4*)&av[c4]);
        float4 g1 = __ldg((const float4*)&av[64 + c4]);
        bb[0] += g0.x; bb[1] += g0.y; bb[2] += g0.z; bb[3] += g0.w;
        bb[4] += g1.x; bb[5] += g1.y; bb[6] += g1.z; bb[7] += g1.w;
    }
    #pragma unroll
    for (int i = 0; i < 8; i++) {
        size_t r = row0 + r4 + (i & 3) + (i >> 2) * 64;
        float4 o0, o1;
        o0.x = acc[i][0] + bb[0]; o0.y = acc[i][1] + bb[1];
        o0.z = acc[i][2] + bb[2]; o0.w = acc[i][3] + bb[3];
        o1.x = acc[i][4] + bb[4]; o1.y = acc[i][5] + bb[5];
        o1.z = acc[i][6] + bb[6]; o1.w = acc[i][7] + bb[7];
        *(float4*)&out[r * 128 + c4] = o0;
        *(float4*)&out[r * 128 + 64 + c4] = o1;
    }
}

__global__ __launch_bounds__(256, 2)
void k_gin(const float* __restrict__ X, const float* __restrict__ W, int w_ld,
           const float* __restrict__ bias, float* __restrict__ out,
           const float* __restrict__ addv) {
    extern __shared__ float smem[];
    float* sA = smem;
    float* sB = smem + 128 * 132;
    int tid = threadIdx.x;
    size_t row0 = (size_t)blockIdx.x * 128;

    // gather stage: sA[r] = X[row0+r] + sum_{src->row0+r} X[src]
    {
        int w = tid >> 5, lane = tid & 31;
        int c = lane * 4;
        #pragma unroll 1
        for (int r16 = 0; r16 < 16; r16++) {
            int lr = w * 16 + r16;
            size_t node = row0 + lr;
            float4 acc = __ldg((const float4*)&X[node * 128 + c]);
            int s0 = g_start[node], d = g_deg[node];
            int e = 0;
            for (; e + 4 <= d; e += 4) {
                int i0 = g_eid[s0 + e], i1 = g_eid[s0 + e + 1];
                int i2 = g_eid[s0 + e + 2], i3 = g_eid[s0 + e + 3];
                float4 v0 = __ldg((const float4*)&X[(size_t)i0 * 128 + c]);
                float4 v1 = __ldg((const float4*)&X[(size_t)i1 * 128 + c]);
                float4 v2 = __ldg((const float4*)&X[(size_t)i2 * 128 + c]);
                float4 v3 = __ldg((const float4*)&X[(size_t)i3 * 128 + c]);
                acc.x += (v0.x + v1.x) + (v2.x + v3.x);
                acc.y += (v0.y + v1.y) + (v2.y + v3.y);
                acc.z += (v0.z + v1.z) + (v2.z + v3.z);
                acc.w += (v0.w + v1.w) + (v2.w + v3.w);
            }
            for (; e < d; e++) {
                int i0 = g_eid[s0 + e];
                float4 v = __ldg((const float4*)&X[(size_t)i0 * 128 + c]);
                acc.x += v.x; acc.y += v.y; acc.z += v.z; acc.w += v.w;
            }
            *(float4*)&sA[lr * 132 + c] = acc;
        }
    }
    __syncthreads();
    gemm_panel(sA, sB, W, w_ld, bias, addv, out, row0, tid);
}

// K and V projections fused: one A-tile load, two B panels.
__global__ __launch_bounds__(256, 2)
void k_kv(const float* __restrict__ X,
          const float* __restrict__ Wk, const float* __restrict__ Wv, int w_ld,
          const float* __restrict__ bk, const float* __restrict__ bv,
          float* __restrict__ outk, float* __restrict__ outv) {
    extern __shared__ float smem[];
    float* sA = smem;
    float* sB = smem + 128 * 132;
    int tid = threadIdx.x;
    size_t row0 = (size_t)blockIdx.x * 128;
    #pragma unroll
    for (int i = 0; i < 16; i++) {
        int r = i * 8 + (tid >> 5);
        int c4 = (tid & 31) * 4;
        *(float4*)&sA[r * 132 + c4] = __ldg((const float4*)&X[(row0 + r) * 128 + c4]);
    }
    __syncthreads();
    gemm_panel(sA, sB, Wk, w_ld, bk, nullptr, outk, row0, tid);
    gemm_panel(sA, sB, Wv, w_ld, bv, nullptr, outv, row0, tid);
}

// ---------------- streamed GEMM for tok (1024 rows) -------------------------
__global__ __launch_bounds__(256, 2)
void k_gemm128(const float* __restrict__ A,
               const float* __restrict__ W, int w_ld,
               const float* __restrict__ bias,
               float* __restrict__ out) {
    __shared__ float sA[2][8][132];
    __shared__ float sB[2][8][128];
    int tid = threadIdx.x;
    size_t row0 = (size_t)blockIdx.x * 128;
    int la_r = tid >> 1;
    int la_k = (tid & 1) * 4;
    int lb_k = tid >> 5;
    int lb_j = (tid & 31) * 4;
    const float* Ap = A + (row0 + la_r) * 128 + la_k;
    const float* Wp = W + lb_j + (size_t)lb_k * w_ld;

    float4 ra = *(const float4*)Ap;
    float4 rb = __ldg((const float4*)Wp);
    sA[0][la_k + 0][la_r] = ra.x; sA[0][la_k + 1][la_r] = ra.y;
    sA[0][la_k + 2][la_r] = ra.z; sA[0][la_k + 3][la_r] = ra.w;
    *(float4*)&sB[0][lb_k][lb_j] = rb;
    __syncthreads();

    int ty = tid >> 4, tx = tid & 15;
    int r4 = ty * 4, c4 = tx * 4;
    float acc[8][8] = {};

    #pragma unroll 1
    for (int c = 0; c < 16; c++) {
        int buf = c & 1;
        if (c < 15) {
            ra = *(const float4*)(Ap + (c + 1) * 8);
            rb = __ldg((const float4*)(Wp + (size_t)(c + 1) * 8 * w_ld));
        }
        #pragma unroll
        for (int k = 0; k < 8; k++) {
            float4 a0 = *(const float4*)&sA[buf][k][r4];
            float4 a1 = *(const float4*)&sA[buf][k][64 + r4];
            float4 b0 = *(const float4*)&sB[buf][k][c4];
            float4 b1 = *(const float4*)&sB[buf][k][64 + c4];
            float av[8] = {a0.x, a0.y, a0.z, a0.w, a1.x, a1.y, a1.z, a1.w};
            float bv[8] = {b0.x, b0.y, b0.z, b0.w, b1.x, b1.y, b1.z, b1.w};
            #pragma unroll
            for (int i = 0; i < 8; i++)
                #pragma unroll
                for (int j = 0; j < 8; j++)
                    acc[i][j] += av[i] * bv[j];
        }
        if (c < 15) {
            int nb = buf ^ 1;
            sA[nb][la_k + 0][la_r] = ra.x; sA[nb][la_k + 1][la_r] = ra.y;
            sA[nb][la_k + 2][la_r] = ra.z; sA[nb][la_k + 3][la_r] = ra.w;
            *(float4*)&sB[nb][lb_k][lb_j] = rb;
            __syncthreads();
        }
    }

    float4 bv0 = *(const float4*)&bias[c4];
    float4 bv1 = *(const float4*)&bias[64 + c4];
    float bb[8] = {bv0.x, bv0.y, bv0.z, bv0.w, bv1.x, bv1.y, bv1.z, bv1.w};
    #pragma unroll
    for (int i = 0; i < 8; i++) {
        size_t r = row0 + r4 + (i & 3) + (i >> 2) * 64;
        float4 o0, o1;
        o0.x = acc[i][0] + bb[0]; o0.y = acc[i][1] + bb[1];
        o0.z = acc[i][2] + bb[2]; o0.w = acc[i][3] + bb[3];
        o1.x = acc[i][4] + bb[4]; o1.y = acc[i][5] + bb[5];
        o1.z = acc[i][6] + bb[6]; o1.w = acc[i][7] + bb[7];
        *(float4*)&out[r * 128 + c4] = o0;
        *(float4*)&out[r * 128 + 64 + c4] = o1;
    }
}

// ---------------- small GEMM for q (8 rows) and final (128 rows) ------------
__global__ void k_matmul(const float* __restrict__ in, int in_ld,
                         const float* __restrict__ W, int w_ld, int w_off,
                         const float* __restrict__ bias, int b_off,
                         float* __restrict__ out, int out_ld, int rows,
                         float bscale) {
    __shared__ float sA[32][128];
    int row0 = blockIdx.x * 32;
    for (int i = threadIdx.x; i < 32 * 128; i += 256) {
        int r = i >> 7, c = i & 127;
        sA[r][c] = (row0 + r < rows) ? in[(size_t)(row0 + r) * in_ld + c] : 0.f;
    }
    __syncthreads();
    int tj = threadIdx.x & 31, tm = threadIdx.x >> 5;
    int j4 = tj * 4;
    float acc[4][4] = {};
    const float* Wp = W + w_off + j4;
    #pragma unroll 4
    for (int k0 = 0; k0 < 128; k0 += 4) {
        float4 a0 = *(const float4*)&sA[tm * 4 + 0][k0];
        float4 a1 = *(const float4*)&sA[tm * 4 + 1][k0];
        float4 a2 = *(const float4*)&sA[tm * 4 + 2][k0];
        float4 a3 = *(const float4*)&sA[tm * 4 + 3][k0];
        float av[4][4] = {{a0.x, a0.y, a0.z, a0.w},
                          {a1.x, a1.y, a1.z, a1.w},
                          {a2.x, a2.y, a2.z, a2.w},
                          {a3.x, a3.y, a3.z, a3.w}};
        #pragma unroll
        for (int kk = 0; kk < 4; kk++) {
            float4 w = __ldg((const float4*)(Wp + (size_t)(k0 + kk) * w_ld));
            #pragma unroll
            for (int m = 0; m < 4; m++) {
                acc[m][0] += av[m][kk] * w.x;
                acc[m][1] += av[m][kk] * w.y;
                acc[m][2] += av[m][kk] * w.z;
                acc[m][3] += av[m][kk] * w.w;
            }
        }
    }
    float4 bv = *(const float4*)&bias[b_off + j4];
    #pragma unroll
    for (int m = 0; m < 4; m++) {
        int r = row0 + tm * 4 + m;
        if (r < rows) {
            float4 o;
            o.x = acc[m][0] + bv.x * bscale; o.y = acc[m][1] + bv.y * bscale;
            o.z = acc[m][2] + bv.z * bscale; o.w = acc[m][3] + bv.w * bscale;
            *(float4*)&out[(size_t)r * out_ld + j4] = o;
        }
    }
}

// ---------------- attention: one block per (graph, head) -------------------
__global__ void k_attn() {
    __shared__ float s_q[8][32];
    __shared__ float s_kt[64 * 37];
    __shared__ float s_sc[8][1024];
    int b = blockIdx.x >> 2, h = blockIdx.x & 3;
    int tid = threadIdx.x;
    {
        int t = tid >> 5, d = tid & 31;
        s_q[t][d] = g_q[t * HH + h * 32 + d];
    }
    __syncthreads();
    int t = tid >> 5, g = tid & 31;
    float qr[32];
    #pragma unroll
    for (int d = 0; d < 32; d++) qr[d] = s_q[t][d];
    const float scale = 0.17677669529663689f;

    for (int kk0 = 0; kk0 < 1024; kk0 += 64) {
        __syncthreads();
        for (int i = tid; i < 64 * 32; i += 256) {
            int key = i >> 5, d = i & 31;
            s_kt[key * 37 + d] = g_k[((size_t)(b * 1024 + kk0 + key)) * HH + h * 32 + d];
        }
        __syncthreads();
        #pragma unroll
        for (int kidx = 0; kidx < 2; kidx++) {
            int key = g + kidx * 32;
            float acc = 0.f;
            #pragma unroll
            for (int d = 0; d < 32; d++) acc += s_kt[key * 37 + d] * qr[d];
            s_sc[t][kk0 + key] = acc * scale;
        }
    }
    __syncthreads();
    float m = -1e30f;
    for (int i = g; i < 1024; i += 32) m = fmaxf(m, s_sc[t][i]);
    #pragma unroll
    for (int d = 16; d; d >>= 1) m = fmaxf(m, __shfl_xor_sync(0xffffffffu, m, d));
    float sum = 0.f;
    for (int i = g; i < 1024; i += 32) {
        float e = __expf(s_sc[t][i] - m);
        s_sc[t][i] = e;
        sum += e;
    }
    #pragma unroll
    for (int d = 16; d; d >>= 1) sum += __shfl_xor_sync(0xffffffffu, sum, d);
    float inv = 1.f / sum;
    for (int i = g; i < 1024; i += 32) s_sc[t][i] *= inv;
    __syncthreads();
    float acc = 0.f;
    const float* vbase = g_v + (size_t)b * 1024 * HH + h * 32 + g;
    #pragma unroll 4
    for (int kk = 0; kk < 1024; kk++)
        acc += s_sc[t][kk] * __ldg(vbase + (size_t)kk * HH);
    g_o[((size_t)b * 8 + t) * HH + h * 32 + g] = acc;
}

// ---------------- mamba: one block per batch element, 256 threads ----------
__global__ void k_mamba(const float* __restrict__ in_w, const float* __restrict__ conv_w,
                        const float* __restrict__ conv_b, const float* __restrict__ x_w,
                        const float* __restrict__ dt_w, const float* __restrict__ dt_b,
                        const float* __restrict__ A_log, const float* __restrict__ Dp,
                        const float* __restrict__ out_w, const float* __restrict__ norm_w,
                        const float* __restrict__ normf_w) {
    __shared__ float s_res[8][128];
    __shared__ float s_h[8][128];
    __shared__ float s_u[8][256];
    __shared__ float s_ssm[8][40];
    __shared__ float s_y[8][256];
    __shared__ float s_o[8][128];
    __shared__ float s_r[8];
    int b = blockIdx.x, tid = threadIdx.x;

    for (int i = tid; i < 8 * 128; i += 256)
        s_res[i >> 7][i & 127] = g_tok[(size_t)b * 1024 + i];
    __syncthreads();
    {
        int t = tid >> 5, lane = tid & 31;
        float ss = 0.f;
        for (int c = lane; c < 128; c += 32) { float v = s_res[t][c]; ss += v * v; }
        #pragma unroll
        for (int d = 16; d; d >>= 1) ss += __shfl_xor_sync(0xffffffffu, ss, d);
        float r = rsqrtf(ss / 128.f + 1e-5f);
        for (int c = lane; c < 128; c += 32) s_h[t][c] = s_res[t][c] * r * norm_w[c];
    }
    __syncthreads();

    int i = tid;
    float u_r[8] = {}, gate_r[8] = {};
    for (int k = 0; k < 128; k++) {
        float w0 = __ldg(&in_w[k * 512 + i]);
        float w1 = __ldg(&in_w[k * 512 + 256 + i]);
        #pragma unroll
        for (int t = 0; t < 8; t++) {
            float hv = s_h[t][k];
            u_r[t] += hv * w0;
            gate_r[t] += hv * w1;
        }
    }
    float cw0 = conv_w[i * 4 + 0], cw1 = conv_w[i * 4 + 1];
    float cw2 = conv_w[i * 4 + 2], cw3 = conv_w[i * 4 + 3];
    float cb = conv_b[i];
    float uc[8];
    #pragma unroll
    for (int t = 0; t < 8; t++) {
        float c = cb + cw3 * u_r[t];
        if (t >= 1) c += cw2 * u_r[t - 1];
        if (t >= 2) c += cw1 * u_r[t - 2];
        if (t >= 3) c += cw0 * u_r[t - 3];
        uc[t] = c / (1.f + expf(-c));
        s_u[t][i] = uc[t];
    }
    __syncthreads();
    for (int idx = tid; idx < 8 * 40; idx += 256) {
        int t = idx / 40, j = idx % 40;
        float a = 0.f;
        for (int k = 0; k < 256; k++) a += s_u[t][k] * __ldg(&x_w[k * 40 + j]);
        s_ssm[t][j] = a;
    }
    __syncthreads();
    float dtv[8];
    {
        float acc[8] = {};
        for (int r = 0; r < 8; r++) {
            float w = __ldg(&dt_w[r * 256 + i]);
            #pragma unroll
            for (int t = 0; t < 8; t++) acc[t] += s_ssm[t][r] * w;
        }
        float db = dt_b[i];
        #pragma unroll
        for (int t = 0; t < 8; t++) {
            float a = acc[t] + db;
            dtv[t] = (a > 20.f) ? a : log1pf(expf(a));
        }
    }
    float Ar[16];
    #pragma unroll
    for (int s = 0; s < 16; s++) Ar[s] = -expf(A_log[i * 16 + s]);
    float Dv = Dp[i];
    float hst[16] = {};
    #pragma unroll
    for (int t = 0; t < 8; t++) {
        float dtt = dtv[t], ut = uc[t];
        float y = 0.f;
        #pragma unroll
        for (int s = 0; s < 16; s++) {
            float dA = expf(dtt * Ar[s]);
            hst[s] = dA * hst[s] + dtt * s_ssm[t][8 + s] * ut;
            y += hst[s] * s_ssm[t][24 + s];
        }
        y += ut * Dv;
        float gt = gate_r[t];
        y *= gt / (1.f + expf(-gt));
        s_y[t][i] = y;
    }
    __syncthreads();
    for (int idx = tid; idx < 8 * 128; idx += 256) {
        int t = idx >> 7, j = idx & 127;
        float a = 0.f;
        for (int k = 0; k < 256; k++) a += s_y[t][k] * __ldg(&out_w[k * 128 + j]);
        s_o[t][j] = s_res[t][j] + a;
    }
    __syncthreads();
    {
        int t = tid >> 5, lane = tid & 31;
        float ss = 0.f;
        for (int c = lane; c < 128; c += 32) { float v = s_o[t][c]; ss += v * v; }
        #pragma unroll
        for (int d = 16; d; d >>= 1) ss += __shfl_xor_sync(0xffffffffu, ss, d);
        if (lane == 0) s_r[t] = rsqrtf(ss / 128.f + 1e-5f);
    }
    __syncthreads();
    if (tid < 128) {
        float a = 0.f;
        #pragma unroll
        for (int t = 0; t < 8; t++) a += s_o[t][tid] * s_r[t];
        g_gf[b * 128 + tid] = a * normf_w[tid] * 0.125f;
    }
}

// ---------------- fused final aggregate + per-graph sum --------------------
// gs[b][j] = sum_{n in b} X[n][j] + sum_{edges e with dst in b} X[src(e)][j]
// grid = 512 (4 parts per graph), block = 512 (4 groups x 128 cols)
__global__ void k_outsum(const float* __restrict__ X) {
    __shared__ float s[512];
    int gid = blockIdx.x;
    int b = gid >> 2, part = gid & 3;
    int tid = threadIdx.x;
    int j = tid & 127, q = tid >> 7;
    int node0 = b * 1024 + part * 256;

    float acc = 0.f, acc2 = 0.f;
    const float* xp = X + (size_t)(node0 + q * 64) * 128 + j;
    #pragma unroll 4
    for (int n = 0; n < 64; n++) acc += xp[(size_t)n * 128];

    int e0 = g_start[node0];
    int e1 = (node0 + 256 < NN) ? g_start[node0 + 256] : EE;
    int e = e0 + q;
    for (; e + 4 < e1; e += 8) {
        int i0 = g_eid[e], i1 = g_eid[e + 4];
        acc  += __ldg(&X[(size_t)i0 * 128 + j]);
        acc2 += __ldg(&X[(size_t)i1 * 128 + j]);
    }
    if (e < e1) acc += __ldg(&X[(size_t)g_eid[e] * 128 + j]);
    acc += acc2;

    s[tid] = acc;
    __syncthreads();
    if (tid < 128)
        atomicAdd(&g_gs[b * 128 + tid], s[tid] + s[tid + 128] + s[tid + 256] + s[tid + 384]);
}

// ---------------- host launch ----------------------------------------------
extern "C" void kernel_launch(void* const* d_in, const int* in_sizes, int n_in,
                              void* d_out, int out_size) {
    int off = (n_in >= 27) ? 0 : -2;
    auto P = [&](int i) -> const void* { return (i < 3) ? d_in[i] : d_in[i + off]; };

    const float* x_in   = (const float*)P(0);
    const int*   ei     = (const int*)P(1);
    const float* w_in   = (const float*)P(5);
    const float* b_in   = (const float*)P(6);
    const float* gin_w  = (const float*)P(7);
    const float* gin_b  = (const float*)P(8);
    const float* vt     = (const float*)P(9);
    const float* qkv_w  = (const float*)P(10);
    const float* qkv_b  = (const float*)P(11);
    const float* ao_w   = (const float*)P(12);
    const float* ao_b   = (const float*)P(13);
    const float* m_in_w   = (const float*)P(14);
    const float* m_conv_w = (const float*)P(15);
    const float* m_conv_b = (const float*)P(16);
    const float* m_x_w    = (const float*)P(17);
    const float* m_dt_w   = (const float*)P(18);
    const float* m_dt_b   = (const float*)P(19);
    const float* m_A_log  = (const float*)P(20);
    const float* m_D      = (const float*)P(21);
    const float* m_out_w  = (const float*)P(22);
    const float* m_norm_w = (const float*)P(23);
    const float* m_normf_w= (const float*)P(24);
    const float* w_out  = (const float*)P(25);
    const float* b_out  = (const float*)P(26);

    float *p_x, *p_x2, *p_k, *p_v, *p_q, *p_o, *p_tok, *p_gf, *p_gs;
    int *p_deg, *p_cursor;
    cudaGetSymbolAddress((void**)&p_x, g_x);
    cudaGetSymbolAddress((void**)&p_x2, g_x2);
    cudaGetSymbolAddress((void**)&p_k, g_k);
    cudaGetSymbolAddress((void**)&p_v, g_v);
    cudaGetSymbolAddress((void**)&p_q, g_q);
    cudaGetSymbolAddress((void**)&p_o, g_o);
    cudaGetSymbolAddress((void**)&p_tok, g_tok);
    cudaGetSymbolAddress((void**)&p_gf, g_gf);
    cudaGetSymbolAddress((void**)&p_gs, g_gs);
    cudaGetSymbolAddress((void**)&p_deg, g_deg);
    cudaGetSymbolAddress((void**)&p_cursor, g_cursor);

    cudaFuncSetAttribute(k_gin, cudaFuncAttributeMaxDynamicSharedMemorySize, SMEM_GIN);
    cudaFuncSetAttribute(k_kv, cudaFuncAttributeMaxDynamicSharedMemorySize, SMEM_GIN);

    // --- CSR build ---
    cudaMemsetAsync(p_deg, 0, NN * sizeof(int));
    cudaMemsetAsync(p_cursor, 0, NN * sizeof(int));
    cudaMemsetAsync(p_gs, 0, BB * HH * sizeof(float));
    k_degree<<<(EE + 255) / 256, 256>>>(ei);
    k_scan1<<<NN / 1024, 1024>>>();
    k_scan2<<<1, 32>>>();
    k_scan3<<<(NN + 255) / 256, 256>>>();
    k_scatter<<<(EE + 255) / 256, 256>>>(ei);

    // --- GIN input layer: x = gin(x_in) ---
    k_gin<<<NN / 128, 256, SMEM_GIN>>>(x_in, w_in, HH, b_in, p_x, nullptr);

    float* xc = p_x;   // current
    float* xn = p_x2;  // next

    for (int l = 0; l < 2; l++) {
        const float* qkvW = qkv_w + (size_t)l * HH * 3 * HH;
        const float* qkvB = qkv_b + (size_t)l * 3 * HH;
        // K, V projections (fused, one A pass)
        k_kv<<<NN / 128, 256, SMEM_GIN>>>(xc, qkvW + HH, qkvW + 2 * HH, 3 * HH,
                                          qkvB + HH, qkvB + 2 * HH, p_k, p_v);
        // q = vt @ Wq + bq
        k_matmul<<<1, 256>>>(vt + l * TT * HH, HH, qkvW, 3 * HH, 0,
                             qkvB, 0, p_q, HH, TT, 1.f);
        k_attn<<<BB * 4, 256>>>();
        // tokens = o @ ao_w + ao_b (1024 rows)
        k_gemm128<<<(BB * TT) / 128, 256>>>(p_o, ao_w + (size_t)l * HH * HH, HH,
                                            ao_b + l * HH, p_tok);
        k_mamba<<<BB, 256>>>(m_in_w, m_conv_w, m_conv_b, m_x_w, m_dt_w, m_dt_b,
                             m_A_log, m_D, m_out_w, m_norm_w, m_normf_w);
        // x_next = gin(x_cur) + gf[batch]   (fused gather + GEMM + epilogue)
        k_gin<<<NN / 128, 256, SMEM_GIN>>>(xc, gin_w + (size_t)l * HH * HH, HH,
                                           gin_b + l * HH, xn, p_gf);
        float* tmp = xc; xc = xn; xn = tmp;
    }

    // --- output: (sum_graph (x + gather(x))) @ w_out + 1024*b_out ---
    k_outsum<<<BB * 4, 512>>>(xc);
    k_matmul<<<BB / 32, 256>>>(p_gs, HH, w_out, HH, 0, b_out, 0,
                               (float*)d_out, HH, BB, 1024.f);
}

// round 7
// speedup vs baseline: 1.2724x; 1.2724x over previous
#include <cuda_runtime.h>
#include <math.h>

// ---------------- problem constants ----------------
#define NN 131072
#define EE 2097152
#define BB 128
#define NPG 1024
#define HH 128
#define TT 8

// ---------------- device scratch ----------------
__device__ float g_x[NN * HH];
__device__ float g_agg[NN * HH];
__device__ float g_sc[NN * 32];        // attention scores: [node][t*4+h]
__device__ float g_q[TT * HH];
__device__ float g_qk[32 * HH];        // folded queries: [(t,h)][c]
__device__ float g_qc[32];             // folded score bias
__device__ float g_o[BB * TT * HH];
__device__ float g_tok[BB * TT * HH];
__device__ float g_gf[BB * HH];
__device__ float g_gs[BB * HH];

__device__ int g_deg[NN];
__device__ int g_start[NN];
__device__ int g_cursor[NN];
__device__ int g_eid[EE];
__device__ int g_bsum[NN / 1024];
__device__ int g_bbase[NN / 1024];

// ---------------- f32x2 packed-FMA helpers ----------------
#define PACK2(d, a)      asm("mov.b64 %0, {%1, %1};" : "=l"(d) : "f"(a))
#define FFMA2(c, a, b)   asm("fma.rn.f32x2 %0, %1, %2, %0;" : "+l"(c) : "l"(a), "l"(b))
#define UNPACK2(lo, hi, v) asm("mov.b64 {%0, %1}, %2;" : "=f"(lo), "=f"(hi) : "l"(v))

// ---------------- CSR build ----------------
__global__ void k_degree(const int* __restrict__ ei) {
    int e = blockIdx.x * 256 + threadIdx.x;
    if (e < EE) atomicAdd(&g_deg[ei[EE + e]], 1);
}

__global__ void k_scan1() {
    __shared__ int wsum[32];
    int i = blockIdx.x * 1024 + threadIdx.x;
    int lane = threadIdx.x & 31, wid = threadIdx.x >> 5;
    int s = g_deg[i];
    #pragma unroll
    for (int d = 1; d < 32; d <<= 1) {
        int t = __shfl_up_sync(0xffffffffu, s, d);
        if (lane >= d) s += t;
    }
    if (lane == 31) wsum[wid] = s;
    __syncthreads();
    if (wid == 0) {
        int ws = wsum[lane];
        #pragma unroll
        for (int d = 1; d < 32; d <<= 1) {
            int t = __shfl_up_sync(0xffffffffu, ws, d);
            if (lane >= d) ws += t;
        }
        wsum[lane] = ws;
    }
    __syncthreads();
    int incl = s + (wid > 0 ? wsum[wid - 1] : 0);
    g_start[i] = incl;
    if (threadIdx.x == 1023) g_bsum[blockIdx.x] = incl;
}

__global__ void k_scan2() {
    int lane = threadIdx.x;
    int base = lane * 4;
    int s0 = g_bsum[base], s1 = g_bsum[base + 1], s2 = g_bsum[base + 2], s3 = g_bsum[base + 3];
    int tot = s0 + s1 + s2 + s3;
    int pre = tot;
    #pragma unroll
    for (int d = 1; d < 32; d <<= 1) {
        int t = __shfl_up_sync(0xffffffffu, pre, d);
        if (lane >= d) pre += t;
    }
    pre -= tot;
    g_bbase[base] = pre;
    g_bbase[base + 1] = pre + s0;
    g_bbase[base + 2] = pre + s0 + s1;
    g_bbase[base + 3] = pre + s0 + s1 + s2;
}

__global__ void k_scan3() {
    int i = blockIdx.x * 256 + threadIdx.x;
    if (i < NN) g_start[i] = g_start[i] - g_deg[i] + g_bbase[i >> 10];
}

__global__ void k_scatter(const int* __restrict__ ei) {
    int e = blockIdx.x * 256 + threadIdx.x;
    if (e < EE) {
        int d = ei[EE + e];
        int p = atomicAdd(&g_cursor[d], 1);
        g_eid[g_start[d] + p] = ei[e];
    }
}

// ---------------- edge aggregation: agg[n] = x[n] + sum_{src->n} x[src] ----
__global__ void k_aggregate(const float* __restrict__ in) {
    int node = blockIdx.x * 8 + (threadIdx.x >> 5);
    int lane = threadIdx.x & 31;
    int c = lane * 4;
    float4 acc = __ldg((const float4*)&in[(size_t)node * HH + c]);
    int s0 = g_start[node];
    int d = g_deg[node];
    int e = 0;
    for (; e + 4 <= d; e += 4) {
        int i0 = g_eid[s0 + e], i1 = g_eid[s0 + e + 1];
        int i2 = g_eid[s0 + e + 2], i3 = g_eid[s0 + e + 3];
        float4 v0 = __ldg((const float4*)&in[(size_t)i0 * HH + c]);
        float4 v1 = __ldg((const float4*)&in[(size_t)i1 * HH + c]);
        float4 v2 = __ldg((const float4*)&in[(size_t)i2 * HH + c]);
        float4 v3 = __ldg((const float4*)&in[(size_t)i3 * HH + c]);
        acc.x += (v0.x + v1.x) + (v2.x + v3.x);
        acc.y += (v0.y + v1.y) + (v2.y + v3.y);
        acc.z += (v0.z + v1.z) + (v2.z + v3.z);
        acc.w += (v0.w + v1.w) + (v2.w + v3.w);
    }
    for (; e < d; e++) {
        int i0 = g_eid[s0 + e];
        float4 v = __ldg((const float4*)&in[(size_t)i0 * HH + c]);
        acc.x += v.x; acc.y += v.y; acc.z += v.z; acc.w += v.w;
    }
    *(float4*)&g_agg[(size_t)node * HH + c] = acc;
}

// ---------------- big SGEMM (f32x2): rows x 128 @ 128 x 128 -----------------
// 128x128 tile, 256 threads, 8x8/thread, double-buffered, packed FFMA2.
__global__ __launch_bounds__(256, 2)
void k_gemm128(const float* __restrict__ A,
               const float* __restrict__ W, int w_ld,
               const float* __restrict__ bias,
               float* __restrict__ out,
               const float* __restrict__ addv) {
    __shared__ float sA[2][8][132];
    __shared__ float sB[2][8][128];
    int tid = threadIdx.x;
    size_t row0 = (size_t)blockIdx.x * 128;
    int la_r = tid >> 1;
    int la_k = (tid & 1) * 4;
    int lb_k = tid >> 5;
    int lb_j = (tid & 31) * 4;
    const float* Ap = A + (row0 + la_r) * 128 + la_k;
    const float* Wp = W + lb_j + (size_t)lb_k * w_ld;

    float4 ra = *(const float4*)Ap;
    float4 rb = __ldg((const float4*)Wp);
    sA[0][la_k + 0][la_r] = ra.x; sA[0][la_k + 1][la_r] = ra.y;
    sA[0][la_k + 2][la_r] = ra.z; sA[0][la_k + 3][la_r] = ra.w;
    *(float4*)&sB[0][lb_k][lb_j] = rb;
    __syncthreads();

    int ty = tid >> 4, tx = tid & 15;
    int r4 = ty * 4, c4 = tx * 4;
    unsigned long long acc2[8][4] = {};

    #pragma unroll 1
    for (int c = 0; c < 16; c++) {
        int buf = c & 1;
        if (c < 15) {
            ra = *(const float4*)(Ap + (c + 1) * 8);
            rb = __ldg((const float4*)(Wp + (size_t)(c + 1) * 8 * w_ld));
        }
        #pragma unroll
        for (int k = 0; k < 8; k++) {
            float4 a0 = *(const float4*)&sA[buf][k][r4];
            float4 a1 = *(const float4*)&sA[buf][k][64 + r4];
            unsigned long long b01 = *(const unsigned long long*)&sB[buf][k][c4];
            unsigned long long b23 = *(const unsigned long long*)&sB[buf][k][c4 + 2];
            unsigned long long b45 = *(const unsigned long long*)&sB[buf][k][64 + c4];
            unsigned long long b67 = *(const unsigned long long*)&sB[buf][k][64 + c4 + 2];
            float av[8] = {a0.x, a0.y, a0.z, a0.w, a1.x, a1.y, a1.z, a1.w};
            #pragma unroll
            for (int i = 0; i < 8; i++) {
                unsigned long long ap;
                PACK2(ap, av[i]);
                FFMA2(acc2[i][0], ap, b01);
                FFMA2(acc2[i][1], ap, b23);
                FFMA2(acc2[i][2], ap, b45);
                FFMA2(acc2[i][3], ap, b67);
            }
        }
        if (c < 15) {
            int nb = buf ^ 1;
            sA[nb][la_k + 0][la_r] = ra.x; sA[nb][la_k + 1][la_r] = ra.y;
            sA[nb][la_k + 2][la_r] = ra.z; sA[nb][la_k + 3][la_r] = ra.w;
            *(float4*)&sB[nb][lb_k][lb_j] = rb;
            __syncthreads();
        }
    }

    float4 bv0 = *(const float4*)&bias[c4];
    float4 bv1 = *(const float4*)&bias[64 + c4];
    float bb[8] = {bv0.x, bv0.y, bv0.z, bv0.w, bv1.x, bv1.y, bv1.z, bv1.w};
    if (addv) {
        const float* av = addv + (row0 >> 10) * 128;
        float4 g0 = __ldg((const float4*)&av[c4]);
        float4 g1 = __ldg((const float4*)&av[64 + c4]);
        bb[0] += g0.x; bb[1] += g0.y; bb[2] += g0.z; bb[3] += g0.w;
        bb[4] += g1.x; bb[5] += g1.y; bb[6] += g1.z; bb[7] += g1.w;
    }
    #pragma unroll
    for (int i = 0; i < 8; i++) {
        size_t r = row0 + r4 + (i & 3) + (i >> 2) * 64;
        float o[8];
        #pragma unroll
        for (int p = 0; p < 4; p++) UNPACK2(o[2 * p], o[2 * p + 1], acc2[i][p]);
        float4 o0, o1;
        o0.x = o[0] + bb[0]; o0.y = o[1] + bb[1]; o0.z = o[2] + bb[2]; o0.w = o[3] + bb[3];
        o1.x = o[4] + bb[4]; o1.y = o[5] + bb[5]; o1.z = o[6] + bb[6]; o1.w = o[7] + bb[7];
        *(float4*)&out[r * 128 + c4] = o0;
        *(float4*)&out[r * 128 + 64 + c4] = o1;
    }
}

// ---------------- small GEMM for q (8 rows) and final (128 rows) ------------
__global__ void k_matmul(const float* __restrict__ in, int in_ld,
                         const float* __restrict__ W, int w_ld, int w_off,
                         const float* __restrict__ bias, int b_off,
                         float* __restrict__ out, int out_ld, int rows,
                         float bscale) {
    __shared__ float sA[32][128];
    int row0 = blockIdx.x * 32;
    for (int i = threadIdx.x; i < 32 * 128; i += 256) {
        int r = i >> 7, c = i & 127;
        sA[r][c] = (row0 + r < rows) ? in[(size_t)(row0 + r) * in_ld + c] : 0.f;
    }
    __syncthreads();
    int tj = threadIdx.x & 31, tm = threadIdx.x >> 5;
    int j4 = tj * 4;
    float acc[4][4] = {};
    const float* Wp = W + w_off + j4;
    #pragma unroll 4
    for (int k0 = 0; k0 < 128; k0 += 4) {
        float4 a0 = *(const float4*)&sA[tm * 4 + 0][k0];
        float4 a1 = *(const float4*)&sA[tm * 4 + 1][k0];
        float4 a2 = *(const float4*)&sA[tm * 4 + 2][k0];
        float4 a3 = *(const float4*)&sA[tm * 4 + 3][k0];
        float av[4][4] = {{a0.x, a0.y, a0.z, a0.w},
                          {a1.x, a1.y, a1.z, a1.w},
                          {a2.x, a2.y, a2.z, a2.w},
                          {a3.x, a3.y, a3.z, a3.w}};
        #pragma unroll
        for (int kk = 0; kk < 4; kk++) {
            float4 w = __ldg((const float4*)(Wp + (size_t)(k0 + kk) * w_ld));
            #pragma unroll
            for (int m = 0; m < 4; m++) {
                acc[m][0] += av[m][kk] * w.x;
                acc[m][1] += av[m][kk] * w.y;
                acc[m][2] += av[m][kk] * w.z;
                acc[m][3] += av[m][kk] * w.w;
            }
        }
    }
    float4 bv = *(const float4*)&bias[b_off + j4];
    #pragma unroll
    for (int m = 0; m < 4; m++) {
        int r = row0 + tm * 4 + m;
        if (r < rows) {
            float4 o;
            o.x = acc[m][0] + bv.x * bscale; o.y = acc[m][1] + bv.y * bscale;
            o.z = acc[m][2] + bv.z * bscale; o.w = acc[m][3] + bv.w * bscale;
            *(float4*)&out[(size_t)r * out_ld + j4] = o;
        }
    }
}

// ---------------- fold W_k into queries: qk[th][c], qc[th] -----------------
// qk[t*4+h][c] = scale * sum_d q[t][h*32+d] * Wk[c][h*32+d]
__global__ void k_qfold(const float* __restrict__ qkvW, const float* __restrict__ qkvB) {
    __shared__ float sq[TT * HH];
    int tid = threadIdx.x;
    const float scale = 0.17677669529663689f;  // 1/sqrt(32)
    for (int i = tid; i < TT * HH; i += 256) sq[i] = g_q[i];
    __syncthreads();
    for (int o = tid; o < 32 * 128; o += 256) {
        int th = o >> 7, c = o & 127;
        int t = th >> 2, h = th & 3;
        const float* wk = qkvW + (size_t)c * 384 + 128 + h * 32;
        const float* qv = sq + t * 128 + h * 32;
        float a = 0.f;
        #pragma unroll
        for (int d = 0; d < 32; d++) a += qv[d] * __ldg(&wk[d]);
        g_qk[th * 128 + c] = a * scale;
    }
    if (tid < 32) {
        int t = tid >> 2, h = tid & 3;
        float a = 0.f;
        #pragma unroll
        for (int d = 0; d < 32; d++)
            a += sq[t * 128 + h * 32 + d] * __ldg(&qkvB[128 + h * 32 + d]);
        g_qc[tid] = a * scale;
    }
}

// ---------------- scores: S[n][th] = x[n] . qk[th] + qc[th] ----------------
#define SMEM_SCORE ((128 * 132 + 128 * 33 + 32) * 4)
__global__ __launch_bounds__(256, 2)
void k_score(const float* __restrict__ X) {
    extern __shared__ float sm[];
    float* sA = sm;                       // 128 x 132
    float* sQ = sm + 128 * 132;           // [k][th], stride 33
    float* sQc = sQ + 128 * 33;
    int tid = threadIdx.x;
    size_t row0 = (size_t)blockIdx.x * 128;
    #pragma unroll
    for (int i = 0; i < 16; i++) {
        int r = i * 8 + (tid >> 5);
        int c4 = (tid & 31) * 4;
        *(float4*)&sA[r * 132 + c4] = __ldg((const float4*)&X[(row0 + r) * 128 + c4]);
    }
    for (int i = tid; i < 128 * 32; i += 256) {
        int th = i & 31, k = i >> 5;
        sQ[k * 33 + th] = g_qk[th * 128 + k];
    }
    if (tid < 32) sQc[tid] = g_qc[tid];
    __syncthreads();

    int w = tid >> 5, lane = tid & 31;
    float acc[16] = {};
    #pragma unroll 4
    for (int k4 = 0; k4 < 128; k4 += 4) {
        float b0 = sQ[(k4 + 0) * 33 + lane];
        float b1 = sQ[(k4 + 1) * 33 + lane];
        float b2 = sQ[(k4 + 2) * 33 + lane];
        float b3 = sQ[(k4 + 3) * 33 + lane];
        #pragma unroll
        for (int r = 0; r < 16; r++) {
            float4 a = *(const float4*)&sA[(w * 16 + r) * 132 + k4];
            acc[r] += a.x * b0 + a.y * b1 + a.z * b2 + a.w * b3;
        }
    }
    float qc = sQc[lane];
    #pragma unroll
    for (int r = 0; r < 16; r++)
        g_sc[(row0 + w * 16 + r) * 32 + lane] = acc[r] + qc;
}

// ---------------- pool: softmax over keys + P = attn @ x + o = P @ Wv ------
// one block per graph, 256 threads
#define SMEM_POOL ((1024 * 32 + 32 * 128 + 32 * 128) * 4)
__global__ __launch_bounds__(256, 1)
void k_pool(const float* __restrict__ X, const float* __restrict__ qkvW,
            const float* __restrict__ qkvB) {
    extern __shared__ float sm[];
    float* sS = sm;                 // 1024 x 32 (scores -> exp weights)
    float* xs = sm + 32768;         // 32 x 128 x-chunk
    float* sP = xs + 4096;          // 32 x 128 pooled
    __shared__ float red[8][32];
    __shared__ float sInv[32];
    const float* Wv = qkvW + 2 * HH;      // ld 384
    const float* bv = qkvB + 2 * HH;
    int b = blockIdx.x, tid = threadIdx.x;
    int w = tid >> 5, lane = tid & 31;

    // load scores for this graph
    {
        const float4* src = (const float4*)(g_sc + (size_t)b * 1024 * 32);
        float4* dst = (float4*)sS;
        for (int i = tid; i < 8192; i += 256) dst[i] = __ldg(&src[i]);
    }
    __syncthreads();
    // softmax stats per th-column (lane = th), warp w owns keys [w*128, w*128+128)
    float mx = -1e30f;
    for (int k = w * 128; k < w * 128 + 128; k++) mx = fmaxf(mx, sS[k * 32 + lane]);
    red[w][lane] = mx;
    __syncthreads();
    mx = red[0][lane];
    #pragma unroll
    for (int i = 1; i < 8; i++) mx = fmaxf(mx, red[i][lane]);
    __syncthreads();
    float sum = 0.f;
    for (int k = w * 128; k < w * 128 + 128; k++) {
        float e = __expf(sS[k * 32 + lane] - mx);
        sS[k * 32 + lane] = e;
        sum += e;
    }
    red[w][lane] = sum;
    __syncthreads();
    if (w == 0) {
        float tot = 0.f;
        #pragma unroll
        for (int i = 0; i < 8; i++) tot += red[i][lane];
        sInv[lane] = 1.f / tot;
    }

    // pooling: P[th][c] = sum_key attnw[key][th] * x[key][c]
    int ty = tid >> 4, tx = tid & 15;   // ty: th-pair, tx: 8-col group
    float acc0[8] = {}, acc1[8] = {};
    for (int c0 = 0; c0 < 1024; c0 += 32) {
        __syncthreads();
        for (int i = tid; i < 1024; i += 256) {
            int row = i >> 5, c4 = (i & 31) * 4;
            *(float4*)&xs[row * 128 + c4] =
                __ldg((const float4*)&X[((size_t)(b * 1024 + c0 + row)) * 128 + c4]);
        }
        __syncthreads();
        #pragma unroll 4
        for (int k = 0; k < 32; k++) {
            float a0 = sS[(c0 + k) * 32 + ty * 2];
            float a1 = sS[(c0 + k) * 32 + ty * 2 + 1];
            float4 x0 = *(const float4*)&xs[k * 128 + tx * 8];
            float4 x1 = *(const float4*)&xs[k * 128 + tx * 8 + 4];
            float xv[8] = {x0.x, x0.y, x0.z, x0.w, x1.x, x1.y, x1.z, x1.w};
            #pragma unroll
            for (int j = 0; j < 8; j++) {
                acc0[j] += a0 * xv[j];
                acc1[j] += a1 * xv[j];
            }
        }
    }
    __syncthreads();
    {
        float i0 = sInv[ty * 2], i1 = sInv[ty * 2 + 1];
        #pragma unroll
        for (int j = 0; j < 8; j++) {
            sP[(ty * 2) * 128 + tx * 8 + j] = acc0[j] * i0;
            sP[(ty * 2 + 1) * 128 + tx * 8 + j] = acc1[j] * i1;
        }
    }
    __syncthreads();
    // o[t][j] = P[t*4 + (j>>5)] . Wv[:, j] + bv[j]
    #pragma unroll
    for (int r = 0; r < 4; r++) {
        int idx = tid + 256 * r;
        int t = idx >> 7, j = idx & 127, h = (j >> 5);
        int row = t * 4 + h;
        float a = __ldg(&bv[j]);
        for (int c = 0; c < 128; c++)
            a += sP[row * 128 + c] * __ldg(&Wv[(size_t)c * 384 + j]);
        g_o[((size_t)b * 8 + t) * 128 + j] = a;
    }
}

// ---------------- mamba: one block per batch element, 256 threads ----------
__global__ void k_mamba(const float* __restrict__ in_w, const float* __restrict__ conv_w,
                        const float* __restrict__ conv_b, const float* __restrict__ x_w,
                        const float* __restrict__ dt_w, const float* __restrict__ dt_b,
                        const float* __restrict__ A_log, const float* __restrict__ Dp,
                        const float* __restrict__ out_w, const float* __restrict__ norm_w,
                        const float* __restrict__ normf_w) {
    __shared__ float s_res[8][128];
    __shared__ float s_h[8][128];
    __shared__ float s_u[8][256];
    __shared__ float s_ssm[8][40];
    __shared__ float s_y[8][256];
    __shared__ float s_o[8][128];
    __shared__ float s_r[8];
    int b = blockIdx.x, tid = threadIdx.x;

    for (int i = tid; i < 8 * 128; i += 256)
        s_res[i >> 7][i & 127] = g_tok[(size_t)b * 1024 + i];
    __syncthreads();
    {
        int t = tid >> 5, lane = tid & 31;
        float ss = 0.f;
        for (int c = lane; c < 128; c += 32) { float v = s_res[t][c]; ss += v * v; }
        #pragma unroll
        for (int d = 16; d; d >>= 1) ss += __shfl_xor_sync(0xffffffffu, ss, d);
        float r = rsqrtf(ss / 128.f + 1e-5f);
        for (int c = lane; c < 128; c += 32) s_h[t][c] = s_res[t][c] * r * norm_w[c];
    }
    __syncthreads();

    int i = tid;
    float u_r[8] = {}, gate_r[8] = {};
    for (int k = 0; k < 128; k++) {
        float w0 = __ldg(&in_w[k * 512 + i]);
        float w1 = __ldg(&in_w[k * 512 + 256 + i]);
        #pragma unroll
        for (int t = 0; t < 8; t++) {
            float hv = s_h[t][k];
            u_r[t] += hv * w0;
            gate_r[t] += hv * w1;
        }
    }
    float cw0 = conv_w[i * 4 + 0], cw1 = conv_w[i * 4 + 1];
    float cw2 = conv_w[i * 4 + 2], cw3 = conv_w[i * 4 + 3];
    float cb = conv_b[i];
    float uc[8];
    #pragma unroll
    for (int t = 0; t < 8; t++) {
        float c = cb + cw3 * u_r[t];
        if (t >= 1) c += cw2 * u_r[t - 1];
        if (t >= 2) c += cw1 * u_r[t - 2];
        if (t >= 3) c += cw0 * u_r[t - 3];
        uc[t] = c / (1.f + expf(-c));
        s_u[t][i] = uc[t];
    }
    __syncthreads();
    for (int idx = tid; idx < 8 * 40; idx += 256) {
        int t = idx / 40, j = idx % 40;
        float a = 0.f;
        for (int k = 0; k < 256; k++) a += s_u[t][k] * __ldg(&x_w[k * 40 + j]);
        s_ssm[t][j] = a;
    }
    __syncthreads();
    float dtv[8];
    {
        float acc[8] = {};
        for (int r = 0; r < 8; r++) {
            float w = __ldg(&dt_w[r * 256 + i]);
            #pragma unroll
            for (int t = 0; t < 8; t++) acc[t] += s_ssm[t][r] * w;
        }
        float db = dt_b[i];
        #pragma unroll
        for (int t = 0; t < 8; t++) {
            float a = acc[t] + db;
            dtv[t] = (a > 20.f) ? a : log1pf(expf(a));
        }
    }
    float Ar[16];
    #pragma unroll
    for (int s = 0; s < 16; s++) Ar[s] = -expf(A_log[i * 16 + s]);
    float Dv = Dp[i];
    float hst[16] = {};
    #pragma unroll
    for (int t = 0; t < 8; t++) {
        float dtt = dtv[t], ut = uc[t];
        float y = 0.f;
        #pragma unroll
        for (int s = 0; s < 16; s++) {
            float dA = expf(dtt * Ar[s]);
            hst[s] = dA * hst[s] + dtt * s_ssm[t][8 + s] * ut;
            y += hst[s] * s_ssm[t][24 + s];
        }
        y += ut * Dv;
        float gt = gate_r[t];
        y *= gt / (1.f + expf(-gt));
        s_y[t][i] = y;
    }
    __syncthreads();
    for (int idx = tid; idx < 8 * 128; idx += 256) {
        int t = idx >> 7, j = idx & 127;
        float a = 0.f;
        for (int k = 0; k < 256; k++) a += s_y[t][k] * __ldg(&out_w[k * 128 + j]);
        s_o[t][j] = s_res[t][j] + a;
    }
    __syncthreads();
    {
        int t = tid >> 5, lane = tid & 31;
        float ss = 0.f;
        for (int c = lane; c < 128; c += 32) { float v = s_o[t][c]; ss += v * v; }
        #pragma unroll
        for (int d = 16; d; d >>= 1) ss += __shfl_xor_sync(0xffffffffu, ss, d);
        if (lane == 0) s_r[t] = rsqrtf(ss / 128.f + 1e-5f);
    }
    __syncthreads();
    if (tid < 128) {
        float a = 0.f;
        #pragma unroll
        for (int t = 0; t < 8; t++) a += s_o[t][tid] * s_r[t];
        g_gf[b * 128 + tid] = a * normf_w[tid] * 0.125f;
    }
}

// ---------------- fused final aggregate + per-graph sum --------------------
__global__ void k_outsum(const float* __restrict__ X) {
    __shared__ float s[512];
    int gid = blockIdx.x;
    int b = gid >> 2, part = gid & 3;
    int tid = threadIdx.x;
    int j = tid & 127, q = tid >> 7;
    int node0 = b * 1024 + part * 256;

    float acc = 0.f, acc2 = 0.f;
    const float* xp = X + (size_t)(node0 + q * 64) * 128 + j;
    #pragma unroll 4
    for (int n = 0; n < 64; n++) acc += xp[(size_t)n * 128];

    int e0 = g_start[node0];
    int e1 = (node0 + 256 < NN) ? g_start[node0 + 256] : EE;
    int e = e0 + q;
    for (; e + 4 < e1; e += 8) {
        int i0 = g_eid[e], i1 = g_eid[e + 4];
        acc  += __ldg(&X[(size_t)i0 * 128 + j]);
        acc2 += __ldg(&X[(size_t)i1 * 128 + j]);
    }
    if (e < e1) acc += __ldg(&X[(size_t)g_eid[e] * 128 + j]);
    acc += acc2;

    s[tid] = acc;
    __syncthreads();
    if (tid < 128)
        atomicAdd(&g_gs[b * 128 + tid], s[tid] + s[tid + 128] + s[tid + 256] + s[tid + 384]);
}

// ---------------- host launch ----------------------------------------------
extern "C" void kernel_launch(void* const* d_in, const int* in_sizes, int n_in,
                              void* d_out, int out_size) {
    int off = (n_in >= 27) ? 0 : -2;
    auto P = [&](int i) -> const void* { return (i < 3) ? d_in[i] : d_in[i + off]; };

    const float* x_in   = (const float*)P(0);
    const int*   ei     = (const int*)P(1);
    const float* w_in   = (const float*)P(5);
    const float* b_in   = (const float*)P(6);
    const float* gin_w  = (const float*)P(7);
    const float* gin_b  = (const float*)P(8);
    const float* vt     = (const float*)P(9);
    const float* qkv_w  = (const float*)P(10);
    const float* qkv_b  = (const float*)P(11);
    const float* ao_w   = (const float*)P(12);
    const float* ao_b   = (const float*)P(13);
    const float* m_in_w   = (const float*)P(14);
    const float* m_conv_w = (const float*)P(15);
    const float* m_conv_b = (const float*)P(16);
    const float* m_x_w    = (const float*)P(17);
    const float* m_dt_w   = (const float*)P(18);
    const float* m_dt_b   = (const float*)P(19);
    const float* m_A_log  = (const float*)P(20);
    const float* m_D      = (const float*)P(21);
    const float* m_out_w  = (const float*)P(22);
    const float* m_norm_w = (const float*)P(23);
    const float* m_normf_w= (const float*)P(24);
    const float* w_out  = (const float*)P(25);
    const float* b_out  = (const float*)P(26);

    float *p_x, *p_agg, *p_q, *p_o, *p_tok, *p_gf, *p_gs;
    int *p_deg, *p_cursor;
    cudaGetSymbolAddress((void**)&p_x, g_x);
    cudaGetSymbolAddress((void**)&p_agg, g_agg);
    cudaGetSymbolAddress((void**)&p_q, g_q);
    cudaGetSymbolAddress((void**)&p_o, g_o);
    cudaGetSymbolAddress((void**)&p_tok, g_tok);
    cudaGetSymbolAddress((void**)&p_gf, g_gf);
    cudaGetSymbolAddress((void**)&p_gs, g_gs);
    cudaGetSymbolAddress((void**)&p_deg, g_deg);
    cudaGetSymbolAddress((void**)&p_cursor, g_cursor);

    cudaFuncSetAttribute(k_score, cudaFuncAttributeMaxDynamicSharedMemorySize, SMEM_SCORE);
    cudaFuncSetAttribute(k_pool, cudaFuncAttributeMaxDynamicSharedMemorySize, SMEM_POOL);

    // --- CSR build ---
    cudaMemsetAsync(p_deg, 0, NN * sizeof(int));
    cudaMemsetAsync(p_cursor, 0, NN * sizeof(int));
    cudaMemsetAsync(p_gs, 0, BB * HH * sizeof(float));
    k_degree<<<(EE + 255) / 256, 256>>>(ei);
    k_scan1<<<NN / 1024, 1024>>>();
    k_scan2<<<1, 32>>>();
    k_scan3<<<(NN + 255) / 256, 256>>>();
    k_scatter<<<(EE + 255) / 256, 256>>>(ei);

    // --- GIN input layer: x = gin(x_in) ---
    k_aggregate<<<NN / 8, 256>>>(x_in);
    k_gemm128<<<NN / 128, 256>>>(p_agg, w_in, HH, b_in, p_x, nullptr);

    for (int l = 0; l < 2; l++) {
        const float* qkvW = qkv_w + (size_t)l * HH * 3 * HH;
        const float* qkvB = qkv_b + (size_t)l * 3 * HH;
        // aggregation for this layer's GIN (reads x)
        k_aggregate<<<NN / 8, 256>>>(p_x);
        // q = vt @ Wq + bq, then fold Wk into q
        k_matmul<<<1, 256>>>(vt + l * TT * HH, HH, qkvW, 3 * HH, 0,
                             qkvB, 0, p_q, HH, TT, 1.f);
        k_qfold<<<1, 256>>>(qkvW, qkvB);
        // scores S = x @ qk^T + qc  (N x 32)
        k_score<<<NN / 128, 256, SMEM_SCORE>>>(p_x);
        // softmax + pool + V projection -> o
        k_pool<<<BB, 256, SMEM_POOL>>>(p_x, qkvW, qkvB);
        // tokens = o @ ao_w + ao_b (1024 rows)
        k_gemm128<<<(BB * TT) / 128, 256>>>(p_o, ao_w + (size_t)l * HH * HH, HH,
                                            ao_b + l * HH, p_tok, nullptr);
        k_mamba<<<BB, 256>>>(m_in_w, m_conv_w, m_conv_b, m_x_w, m_dt_w, m_dt_b,
                             m_A_log, m_D, m_out_w, m_norm_w, m_normf_w);
        // x = gin(x) + gf[batch]  (reads agg, overwrites x in place)
        k_gemm128<<<NN / 128, 256>>>(p_agg, gin_w + (size_t)l * HH * HH, HH,
                                     gin_b + l * HH, p_x, p_gf);
    }

    // --- output: (sum_graph (x + gather(x))) @ w_out + 1024*b_out ---
    k_outsum<<<BB * 4, 512>>>(p_x);
    k_matmul<<<BB / 32, 256>>>(p_gs, HH, w_out, HH, 0, b_out, 0,
                               (float*)d_out, HH, BB, 1024.f);
}